// round 6
// baseline (speedup 1.0000x reference)
#include <cuda_runtime.h>
#include <cuda_bf16.h>
#include <cstdint>

#define NROWS 8192
#define KDIM  128
#define GAMMA_F 0.005f   // 1/(2*10^2)

#define TILE 128
#define THREADS 256

// SMEM: padded bf16 tiles, row stride 272 bytes (128 bf16 = 256B + 16B pad)
#define ROW_BYTES 272
#define TILE_BYTES (TILE * ROW_BYTES)          // 34816
#define SMEM_A  0
#define SMEM_B  TILE_BYTES                      // 34816
#define SMEM_N1 (2 * TILE_BYTES)                // 69632
#define SMEM_N2 (SMEM_N1 + TILE * 4)            // 70144
#define SMEM_TOTAL (SMEM_N2 + TILE * 4)         // 70656

static __device__ __forceinline__ uint32_t smem_u32(const void* p) {
    uint32_t a;
    asm("{ .reg .u64 t; cvta.to.shared.u64 t, %1; cvt.u32.u64 %0, t; }"
        : "=r"(a) : "l"(p));
    return a;
}

static __device__ __forceinline__ void ldsm_x4(uint32_t& r0, uint32_t& r1,
                                               uint32_t& r2, uint32_t& r3,
                                               uint32_t addr) {
    asm volatile("ldmatrix.sync.aligned.m8n8.x4.shared.b16 {%0,%1,%2,%3}, [%4];"
                 : "=r"(r0), "=r"(r1), "=r"(r2), "=r"(r3) : "r"(addr));
}

static __device__ __forceinline__ void mma_16816(float* d,
                                                 const uint32_t* a,
                                                 uint32_t b0, uint32_t b1) {
    asm volatile(
        "mma.sync.aligned.m16n8k16.row.col.f32.bf16.bf16.f32 "
        "{%0,%1,%2,%3}, {%4,%5,%6,%7}, {%8,%9}, {%0,%1,%2,%3};"
        : "+f"(d[0]), "+f"(d[1]), "+f"(d[2]), "+f"(d[3])
        : "r"(a[0]), "r"(a[1]), "r"(a[2]), "r"(a[3]), "r"(b0), "r"(b1));
}

// ---------------- fused kernel ----------------
__global__ void __launch_bounds__(THREADS, 3)
rbf_mma_kernel(const float* __restrict__ x1,
               const float* __restrict__ x2,
               float* __restrict__ out)
{
    extern __shared__ char smem[];
    uint32_t sbase = smem_u32(smem);
    int tid = threadIdx.x;
    int wid = tid >> 5;
    int lane = tid & 31;

    int rowBase = blockIdx.y * TILE;
    int colBase = blockIdx.x * TILE;

    float* sn1 = reinterpret_cast<float*>(smem + SMEM_N1);
    float* sn2 = reinterpret_cast<float*>(smem + SMEM_N2);

    // ---- load tiles fp32 -> bf16 into padded SMEM, fused norm reduction ----
    // Per iteration each warp owns exactly one row: row = 8*it + wid, c4 = lane.
    {
        const float4* a4 = reinterpret_cast<const float4*>(x1 + (size_t)rowBase * KDIM);
        const float4* b4 = reinterpret_cast<const float4*>(x2 + (size_t)colBase * KDIM);
        #pragma unroll
        for (int it = 0; it < (TILE * 32) / THREADS; ++it) {
            int row = 8 * it + wid;
            int c4  = lane;
            float4 va = a4[(size_t)row * 32 + c4];
            float4 vb = b4[(size_t)row * 32 + c4];

            float sa = va.x * va.x + va.y * va.y + va.z * va.z + va.w * va.w;
            float sb = vb.x * vb.x + vb.y * vb.y + vb.z * vb.z + vb.w * vb.w;
            #pragma unroll
            for (int m = 16; m > 0; m >>= 1) {
                sa += __shfl_xor_sync(0xFFFFFFFFu, sa, m);
                sb += __shfl_xor_sync(0xFFFFFFFFu, sb, m);
            }
            if (lane == 0) { sn1[row] = sa; sn2[row] = sb; }

            __nv_bfloat162 a0 = __floats2bfloat162_rn(va.x, va.y);
            __nv_bfloat162 a1 = __floats2bfloat162_rn(va.z, va.w);
            __nv_bfloat162 b0 = __floats2bfloat162_rn(vb.x, vb.y);
            __nv_bfloat162 b1 = __floats2bfloat162_rn(vb.z, vb.w);
            uint32_t off = (uint32_t)row * ROW_BYTES + (uint32_t)c4 * 8;
            *reinterpret_cast<uint2*>(smem + SMEM_A + off) =
                make_uint2(*reinterpret_cast<uint32_t*>(&a0), *reinterpret_cast<uint32_t*>(&a1));
            *reinterpret_cast<uint2*>(smem + SMEM_B + off) =
                make_uint2(*reinterpret_cast<uint32_t*>(&b0), *reinterpret_cast<uint32_t*>(&b1));
        }
    }
    __syncthreads();

    // ---- mma mainloop: warp grid 2(M) x 4(N); each warp 64x32 ----
    int mw = wid >> 2;       // 0..1
    int nw = wid & 3;        // 0..3

    float acc[4][4][4];      // [mi][ni][reg]
    #pragma unroll
    for (int mi = 0; mi < 4; ++mi)
        #pragma unroll
        for (int ni = 0; ni < 4; ++ni)
            #pragma unroll
            for (int r = 0; r < 4; ++r) acc[mi][ni][r] = 0.0f;

    uint32_t lrow  = lane & 15;
    uint32_t lhalf = (lane >> 4) * 16;   // byte offset of k-half

    #pragma unroll
    for (int ks = 0; ks < 8; ++ks) {
        uint32_t koff = (uint32_t)ks * 32 + lhalf;

        uint32_t af[4][4];
        #pragma unroll
        for (int mi = 0; mi < 4; ++mi) {
            uint32_t row = (uint32_t)(mw * 64 + mi * 16) + lrow;
            ldsm_x4(af[mi][0], af[mi][1], af[mi][2], af[mi][3],
                    sbase + SMEM_A + row * ROW_BYTES + koff);
        }
        uint32_t bf[2][4];
        #pragma unroll
        for (int nj = 0; nj < 2; ++nj) {
            uint32_t row = (uint32_t)(nw * 32 + nj * 16) + lrow;
            ldsm_x4(bf[nj][0], bf[nj][1], bf[nj][2], bf[nj][3],
                    sbase + SMEM_B + row * ROW_BYTES + koff);
        }
        #pragma unroll
        for (int mi = 0; mi < 4; ++mi) {
            #pragma unroll
            for (int ni = 0; ni < 4; ++ni) {
                int nj = ni >> 1, sub = ni & 1;
                mma_16816(acc[mi][ni], af[mi], bf[nj][sub], bf[nj][sub + 2]);
            }
        }
    }

    // ---- epilogue: xor-shuffle merge to float4, exp, coalesced STG.128 ----
    // Lane layout per row-group: lane = qr*4 + qi, thread owns cols qc=2*qi, qc+1
    // of each n8 tile. Pair lanes (qi even/odd) exchange one float2 so each
    // thread ends with 4 CONTIGUOUS columns of one row -> STG.128.
    {
        int qr = lane >> 2;          // 0..7 (row within 8-row group)
        int qi = lane & 3;           // 0..3
        int odd = qi & 1;

        #pragma unroll
        for (int mi = 0; mi < 4; ++mi) {
            #pragma unroll
            for (int p = 0; p < 2; ++p) {        // tile pair (2p, 2p+1)
                const float* a = acc[mi][2 * p];      // tile ni=2p
                const float* b = acc[mi][2 * p + 1];  // tile ni=2p+1
                #pragma unroll
                for (int h = 0; h < 2; ++h) {    // row half: qr, qr+8
                    // even lanes send their b-pair, odd lanes send their a-pair
                    float s0 = odd ? a[2 * h]     : b[2 * h];
                    float s1 = odd ? a[2 * h + 1] : b[2 * h + 1];
                    float r0 = __shfl_xor_sync(0xFFFFFFFFu, s0, 1);
                    float r1 = __shfl_xor_sync(0xFFFFFFFFu, s1, 1);

                    float c0, c1, c2, c3;
                    if (odd) { c0 = r0; c1 = r1; c2 = b[2 * h]; c3 = b[2 * h + 1]; }
                    else     { c0 = a[2 * h]; c1 = a[2 * h + 1]; c2 = r0; c3 = r1; }

                    int col = nw * 32 + p * 16 + odd * 8 + (qi & 2) * 2;  // mult of 4
                    int row = mw * 64 + mi * 16 + h * 8 + qr;

                    float n1v = sn1[row];
                    float4 n2v = *reinterpret_cast<const float4*>(sn2 + col);
                    float4 o;
                    o.x = __expf(-GAMMA_F * (n1v + n2v.x - 2.0f * c0));
                    o.y = __expf(-GAMMA_F * (n1v + n2v.y - 2.0f * c1));
                    o.z = __expf(-GAMMA_F * (n1v + n2v.z - 2.0f * c2));
                    o.w = __expf(-GAMMA_F * (n1v + n2v.w - 2.0f * c3));
                    *reinterpret_cast<float4*>(
                        out + (size_t)(rowBase + row) * NROWS + colBase + col) = o;
                }
            }
        }
    }
}

// ---------------- launch ----------------
extern "C" void kernel_launch(void* const* d_in, const int* in_sizes, int n_in,
                              void* d_out, int out_size)
{
    const float* x1 = (const float*)d_in[0];
    const float* x2 = (const float*)d_in[1];
    float* out = (float*)d_out;

    cudaFuncSetAttribute(rbf_mma_kernel,
                         cudaFuncAttributeMaxDynamicSharedMemorySize, SMEM_TOTAL);
    cudaFuncSetAttribute(rbf_mma_kernel,
                         cudaFuncAttributePreferredSharedMemoryCarveout, 100);

    dim3 grid(NROWS / TILE, NROWS / TILE);   // 64 x 64
    rbf_mma_kernel<<<grid, THREADS, SMEM_TOTAL>>>(x1, x2, out);
}

// round 7
// speedup vs baseline: 1.0971x; 1.0971x over previous
#include <cuda_runtime.h>
#include <cuda_bf16.h>
#include <cstdint>

#define NROWS 8192
#define KDIM  128
#define GAMMA_F 0.005f   // 1/(2*10^2)

#define TILE 128
#define THREADS 256

// SMEM: padded bf16 tiles, row stride 272 bytes (128 bf16 = 256B + 16B pad)
#define ROW_BYTES 272
#define TILE_BYTES (TILE * ROW_BYTES)          // 34816
#define SMEM_A  0
#define SMEM_B  TILE_BYTES                      // 34816
#define SMEM_N1 (2 * TILE_BYTES)                // 69632
#define SMEM_N2 (SMEM_N1 + TILE * 4)            // 70144
#define SMEM_TOTAL (SMEM_N2 + TILE * 4)         // 70656

static __device__ __forceinline__ uint32_t smem_u32(const void* p) {
    uint32_t a;
    asm("{ .reg .u64 t; cvta.to.shared.u64 t, %1; cvt.u32.u64 %0, t; }"
        : "=r"(a) : "l"(p));
    return a;
}

static __device__ __forceinline__ void ldsm_x4(uint32_t& r0, uint32_t& r1,
                                               uint32_t& r2, uint32_t& r3,
                                               uint32_t addr) {
    asm volatile("ldmatrix.sync.aligned.m8n8.x4.shared.b16 {%0,%1,%2,%3}, [%4];"
                 : "=r"(r0), "=r"(r1), "=r"(r2), "=r"(r3) : "r"(addr));
}

static __device__ __forceinline__ void mma_16816(float* d,
                                                 const uint32_t* a,
                                                 uint32_t b0, uint32_t b1) {
    asm volatile(
        "mma.sync.aligned.m16n8k16.row.col.f32.bf16.bf16.f32 "
        "{%0,%1,%2,%3}, {%4,%5,%6,%7}, {%8,%9}, {%0,%1,%2,%3};"
        : "+f"(d[0]), "+f"(d[1]), "+f"(d[2]), "+f"(d[3])
        : "r"(a[0]), "r"(a[1]), "r"(a[2]), "r"(a[3]), "r"(b0), "r"(b1));
}

// ---------------- fused kernel ----------------
__global__ void __launch_bounds__(THREADS)
rbf_mma_kernel(const float* __restrict__ x1,
               const float* __restrict__ x2,
               float* __restrict__ out)
{
    extern __shared__ char smem[];
    uint32_t sbase = smem_u32(smem);
    int tid = threadIdx.x;
    int wid = tid >> 5;
    int lane = tid & 31;

    int rowBase = blockIdx.y * TILE;
    int colBase = blockIdx.x * TILE;

    float* sn1 = reinterpret_cast<float*>(smem + SMEM_N1);
    float* sn2 = reinterpret_cast<float*>(smem + SMEM_N2);

    // ---- load tiles fp32 -> bf16 into padded SMEM, fused norm reduction ----
    // Per iteration each warp owns exactly one row: row = 8*it + wid, c4 = lane.
    {
        const float4* a4 = reinterpret_cast<const float4*>(x1 + (size_t)rowBase * KDIM);
        const float4* b4 = reinterpret_cast<const float4*>(x2 + (size_t)colBase * KDIM);
        #pragma unroll
        for (int it = 0; it < (TILE * 32) / THREADS; ++it) {
            int row = 8 * it + wid;
            int c4  = lane;
            float4 va = a4[(size_t)row * 32 + c4];
            float4 vb = b4[(size_t)row * 32 + c4];

            float sa = va.x * va.x + va.y * va.y + va.z * va.z + va.w * va.w;
            float sb = vb.x * vb.x + vb.y * vb.y + vb.z * vb.z + vb.w * vb.w;
            #pragma unroll
            for (int m = 16; m > 0; m >>= 1) {
                sa += __shfl_xor_sync(0xFFFFFFFFu, sa, m);
                sb += __shfl_xor_sync(0xFFFFFFFFu, sb, m);
            }
            if (lane == 0) { sn1[row] = sa; sn2[row] = sb; }

            __nv_bfloat162 a0 = __floats2bfloat162_rn(va.x, va.y);
            __nv_bfloat162 a1 = __floats2bfloat162_rn(va.z, va.w);
            __nv_bfloat162 b0 = __floats2bfloat162_rn(vb.x, vb.y);
            __nv_bfloat162 b1 = __floats2bfloat162_rn(vb.z, vb.w);
            uint32_t off = (uint32_t)row * ROW_BYTES + (uint32_t)c4 * 8;
            *reinterpret_cast<uint2*>(smem + SMEM_A + off) =
                make_uint2(*reinterpret_cast<uint32_t*>(&a0), *reinterpret_cast<uint32_t*>(&a1));
            *reinterpret_cast<uint2*>(smem + SMEM_B + off) =
                make_uint2(*reinterpret_cast<uint32_t*>(&b0), *reinterpret_cast<uint32_t*>(&b1));
        }
    }
    __syncthreads();

    // ---- mma mainloop: warp grid 2(M) x 4(N); each warp 64x32 ----
    int mw = wid >> 2;       // 0..1
    int nw = wid & 3;        // 0..3

    float acc[4][4][4];      // [mi][ni][reg]
    #pragma unroll
    for (int mi = 0; mi < 4; ++mi)
        #pragma unroll
        for (int ni = 0; ni < 4; ++ni)
            #pragma unroll
            for (int r = 0; r < 4; ++r) acc[mi][ni][r] = 0.0f;

    uint32_t lrow  = lane & 15;
    uint32_t lhalf = (lane >> 4) * 16;   // byte offset of k-half

    #pragma unroll
    for (int ks = 0; ks < 8; ++ks) {
        uint32_t koff = (uint32_t)ks * 32 + lhalf;

        uint32_t af[4][4];
        #pragma unroll
        for (int mi = 0; mi < 4; ++mi) {
            uint32_t row = (uint32_t)(mw * 64 + mi * 16) + lrow;
            ldsm_x4(af[mi][0], af[mi][1], af[mi][2], af[mi][3],
                    sbase + SMEM_A + row * ROW_BYTES + koff);
        }
        uint32_t bf[2][4];
        #pragma unroll
        for (int nj = 0; nj < 2; ++nj) {
            uint32_t row = (uint32_t)(nw * 32 + nj * 16) + lrow;
            ldsm_x4(bf[nj][0], bf[nj][1], bf[nj][2], bf[nj][3],
                    sbase + SMEM_B + row * ROW_BYTES + koff);
        }
        #pragma unroll
        for (int mi = 0; mi < 4; ++mi) {
            #pragma unroll
            for (int ni = 0; ni < 4; ++ni) {
                int nj = ni >> 1, sub = ni & 1;
                mma_16816(acc[mi][ni], af[mi], bf[nj][sub], bf[nj][sub + 2]);
            }
        }
    }

    // ---- epilogue: xor-shuffle merge to float4, exp, coalesced STG.128 ----
    // Lane layout per row-group: lane = qr*4 + qi, thread owns cols qc=2*qi, qc+1
    // of each n8 tile. Pair lanes (qi even/odd) exchange one float2 so each
    // thread ends with 4 CONTIGUOUS columns of one row -> STG.128.
    {
        int qr = lane >> 2;          // 0..7 (row within 8-row group)
        int qi = lane & 3;           // 0..3
        int odd = qi & 1;

        #pragma unroll
        for (int mi = 0; mi < 4; ++mi) {
            #pragma unroll
            for (int p = 0; p < 2; ++p) {        // tile pair (2p, 2p+1)
                const float* a = acc[mi][2 * p];      // tile ni=2p
                const float* b = acc[mi][2 * p + 1];  // tile ni=2p+1
                #pragma unroll
                for (int h = 0; h < 2; ++h) {    // row half: qr, qr+8
                    // even lanes send their b-pair, odd lanes send their a-pair
                    float s0 = odd ? a[2 * h]     : b[2 * h];
                    float s1 = odd ? a[2 * h + 1] : b[2 * h + 1];
                    float r0 = __shfl_xor_sync(0xFFFFFFFFu, s0, 1);
                    float r1 = __shfl_xor_sync(0xFFFFFFFFu, s1, 1);

                    float c0, c1, c2, c3;
                    if (odd) { c0 = r0; c1 = r1; c2 = b[2 * h]; c3 = b[2 * h + 1]; }
                    else     { c0 = a[2 * h]; c1 = a[2 * h + 1]; c2 = r0; c3 = r1; }

                    int col = nw * 32 + p * 16 + odd * 8 + (qi & 2) * 2;  // mult of 4
                    int row = mw * 64 + mi * 16 + h * 8 + qr;

                    float n1v = sn1[row];
                    float4 n2v = *reinterpret_cast<const float4*>(sn2 + col);
                    float4 o;
                    o.x = __expf(-GAMMA_F * (n1v + n2v.x - 2.0f * c0));
                    o.y = __expf(-GAMMA_F * (n1v + n2v.y - 2.0f * c1));
                    o.z = __expf(-GAMMA_F * (n1v + n2v.z - 2.0f * c2));
                    o.w = __expf(-GAMMA_F * (n1v + n2v.w - 2.0f * c3));
                    *reinterpret_cast<float4*>(
                        out + (size_t)(rowBase + row) * NROWS + colBase + col) = o;
                }
            }
        }
    }
}

// ---------------- launch ----------------
extern "C" void kernel_launch(void* const* d_in, const int* in_sizes, int n_in,
                              void* d_out, int out_size)
{
    const float* x1 = (const float*)d_in[0];
    const float* x2 = (const float*)d_in[1];
    float* out = (float*)d_out;

    cudaFuncSetAttribute(rbf_mma_kernel,
                         cudaFuncAttributeMaxDynamicSharedMemorySize, SMEM_TOTAL);
    cudaFuncSetAttribute(rbf_mma_kernel,
                         cudaFuncAttributePreferredSharedMemoryCarveout, 100);

    dim3 grid(NROWS / TILE, NROWS / TILE);   // 64 x 64
    rbf_mma_kernel<<<grid, THREADS, SMEM_TOTAL>>>(x1, x2, out);
}

// round 8
// speedup vs baseline: 1.2529x; 1.1420x over previous
#include <cuda_runtime.h>
#include <cuda_bf16.h>
#include <cstdint>

#define NROWS 8192
#define KDIM  128
#define GAMMA_F 0.005f   // 1/(2*10^2)

#define TILE 128
#define THREADS 256
#define CTILES 4          // column tiles per CTA (strip mining)

// SMEM: padded bf16 tiles, row stride 272 bytes (128 bf16 = 256B + 16B pad)
#define ROW_BYTES 272
#define TILE_BYTES (TILE * ROW_BYTES)          // 34816
#define SMEM_A  0
#define SMEM_B  TILE_BYTES                      // 34816
#define SMEM_N1 (2 * TILE_BYTES)                // 69632
#define SMEM_N2 (SMEM_N1 + TILE * 4)            // 70144
#define SMEM_TOTAL (SMEM_N2 + TILE * 4)         // 70656

static __device__ __forceinline__ uint32_t smem_u32(const void* p) {
    uint32_t a;
    asm("{ .reg .u64 t; cvta.to.shared.u64 t, %1; cvt.u32.u64 %0, t; }"
        : "=r"(a) : "l"(p));
    return a;
}

static __device__ __forceinline__ void ldsm_x4(uint32_t& r0, uint32_t& r1,
                                               uint32_t& r2, uint32_t& r3,
                                               uint32_t addr) {
    asm volatile("ldmatrix.sync.aligned.m8n8.x4.shared.b16 {%0,%1,%2,%3}, [%4];"
                 : "=r"(r0), "=r"(r1), "=r"(r2), "=r"(r3) : "r"(addr));
}

static __device__ __forceinline__ void mma_16816(float* d,
                                                 const uint32_t* a,
                                                 uint32_t b0, uint32_t b1) {
    asm volatile(
        "mma.sync.aligned.m16n8k16.row.col.f32.bf16.bf16.f32 "
        "{%0,%1,%2,%3}, {%4,%5,%6,%7}, {%8,%9}, {%0,%1,%2,%3};"
        : "+f"(d[0]), "+f"(d[1]), "+f"(d[2]), "+f"(d[3])
        : "r"(a[0]), "r"(a[1]), "r"(a[2]), "r"(a[3]), "r"(b0), "r"(b1));
}

// Load one 128x128 fp32 tile -> bf16 padded SMEM + fp32 row norms.
// Per iteration each warp owns one row: row = 8*it + wid, lane = float4 idx.
static __device__ __forceinline__ void load_tile(const float* __restrict__ src,
                                                 char* smem_tile, float* snorm,
                                                 int wid, int lane) {
    const float4* s4 = reinterpret_cast<const float4*>(src);
    #pragma unroll
    for (int it = 0; it < 16; ++it) {
        int row = 8 * it + wid;
        float4 v = s4[(size_t)row * 32 + lane];
        float s = v.x * v.x + v.y * v.y + v.z * v.z + v.w * v.w;
        #pragma unroll
        for (int m = 16; m > 0; m >>= 1)
            s += __shfl_xor_sync(0xFFFFFFFFu, s, m);
        if (lane == 0) snorm[row] = s;
        __nv_bfloat162 p0 = __floats2bfloat162_rn(v.x, v.y);
        __nv_bfloat162 p1 = __floats2bfloat162_rn(v.z, v.w);
        uint32_t off = (uint32_t)row * ROW_BYTES + (uint32_t)lane * 8;
        *reinterpret_cast<uint2*>(smem_tile + off) =
            make_uint2(*reinterpret_cast<uint32_t*>(&p0), *reinterpret_cast<uint32_t*>(&p1));
    }
}

// ---------------- fused strip kernel ----------------
__global__ void __launch_bounds__(THREADS)
rbf_mma_kernel(const float* __restrict__ x1,
               const float* __restrict__ x2,
               float* __restrict__ out)
{
    extern __shared__ char smem[];
    uint32_t sbase = smem_u32(smem);
    int tid = threadIdx.x;
    int wid = tid >> 5;
    int lane = tid & 31;

    int rowBase = blockIdx.y * TILE;

    float* sn1 = reinterpret_cast<float*>(smem + SMEM_N1);
    float* sn2 = reinterpret_cast<float*>(smem + SMEM_N2);

    // ---- A tile + n1: once per strip ----
    load_tile(x1 + (size_t)rowBase * KDIM, smem + SMEM_A, sn1, wid, lane);

    int mw = wid >> 2;       // 0..1
    int nw = wid & 3;        // 0..3
    uint32_t lrow  = lane & 15;
    uint32_t lhalf = (lane >> 4) * 16;   // byte offset of k-half

    for (int ct = 0; ct < CTILES; ++ct) {
        int colBase = (blockIdx.x * CTILES + ct) * TILE;

        // ---- B tile + n2 ----
        load_tile(x2 + (size_t)colBase * KDIM, smem + SMEM_B, sn2, wid, lane);
        __syncthreads();

        // ---- mma mainloop: warp grid 2(M) x 4(N); each warp 64x32 ----
        float acc[4][4][4];
        #pragma unroll
        for (int mi = 0; mi < 4; ++mi)
            #pragma unroll
            for (int ni = 0; ni < 4; ++ni)
                #pragma unroll
                for (int r = 0; r < 4; ++r) acc[mi][ni][r] = 0.0f;

        #pragma unroll
        for (int ks = 0; ks < 8; ++ks) {
            uint32_t koff = (uint32_t)ks * 32 + lhalf;

            uint32_t af[4][4];
            #pragma unroll
            for (int mi = 0; mi < 4; ++mi) {
                uint32_t row = (uint32_t)(mw * 64 + mi * 16) + lrow;
                ldsm_x4(af[mi][0], af[mi][1], af[mi][2], af[mi][3],
                        sbase + SMEM_A + row * ROW_BYTES + koff);
            }
            uint32_t bf[2][4];
            #pragma unroll
            for (int nj = 0; nj < 2; ++nj) {
                uint32_t row = (uint32_t)(nw * 32 + nj * 16) + lrow;
                ldsm_x4(bf[nj][0], bf[nj][1], bf[nj][2], bf[nj][3],
                        sbase + SMEM_B + row * ROW_BYTES + koff);
            }
            #pragma unroll
            for (int mi = 0; mi < 4; ++mi) {
                #pragma unroll
                for (int ni = 0; ni < 4; ++ni) {
                    int nj = ni >> 1, sub = ni & 1;
                    mma_16816(acc[mi][ni], af[mi], bf[nj][sub], bf[nj][sub + 2]);
                }
            }
        }

        // ---- R4 epilogue: exp directly on acc, STG.64, no cross-lane deps ----
        {
            int qr = lane >> 2;          // 0..7
            int qc = (lane & 3) * 2;     // 0,2,4,6

            #pragma unroll
            for (int mi = 0; mi < 4; ++mi) {
                int row0 = mw * 64 + mi * 16 + qr;       // rows row0, row0+8
                float n1a = sn1[row0];
                float n1b = sn1[row0 + 8];
                float* out0 = out + (size_t)(rowBase + row0) * NROWS + colBase;
                float* out1 = out0 + (size_t)8 * NROWS;
                #pragma unroll
                for (int ni = 0; ni < 4; ++ni) {
                    int col = nw * 32 + ni * 8 + qc;
                    float n2a = sn2[col];
                    float n2b = sn2[col + 1];
                    float2 oa, ob;
                    oa.x = __expf(-GAMMA_F * (n1a + n2a - 2.0f * acc[mi][ni][0]));
                    oa.y = __expf(-GAMMA_F * (n1a + n2b - 2.0f * acc[mi][ni][1]));
                    ob.x = __expf(-GAMMA_F * (n1b + n2a - 2.0f * acc[mi][ni][2]));
                    ob.y = __expf(-GAMMA_F * (n1b + n2b - 2.0f * acc[mi][ni][3]));
                    *reinterpret_cast<float2*>(out0 + col) = oa;
                    *reinterpret_cast<float2*>(out1 + col) = ob;
                }
            }
        }
        __syncthreads();   // B tile / sn2 consumed; safe to overwrite next iter
    }
}

// ---------------- launch ----------------
extern "C" void kernel_launch(void* const* d_in, const int* in_sizes, int n_in,
                              void* d_out, int out_size)
{
    const float* x1 = (const float*)d_in[0];
    const float* x2 = (const float*)d_in[1];
    float* out = (float*)d_out;

    cudaFuncSetAttribute(rbf_mma_kernel,
                         cudaFuncAttributeMaxDynamicSharedMemorySize, SMEM_TOTAL);
    cudaFuncSetAttribute(rbf_mma_kernel,
                         cudaFuncAttributePreferredSharedMemoryCarveout, 100);

    dim3 grid(NROWS / (TILE * CTILES), NROWS / TILE);   // 16 x 64
    rbf_mma_kernel<<<grid, THREADS, SMEM_TOTAL>>>(x1, x2, out);
}